// round 17
// baseline (speedup 1.0000x reference)
#include <cuda_runtime.h>
#include <cuda_fp16.h>
#include <math.h>
#include <stdint.h>

#define BB 8
#define SS 1024
#define EE 1024
#define HH 16
#define DD 64
#define LL 2
#define MROWS (BB*SS)              // 8192
#define OUT_MAIN (BB*SS*EE)        // 8388608
#define OFF_PROBS OUT_MAIN
#define OFF_MODE  (OUT_MAIN + 8)
#define OFF_MEAN  (OUT_MAIN + 16)

// ---------------- scratch (device globals; no allocation allowed) ------------
__device__ float g_bufA[MROWS * EE];     // out-proj fp32
__device__ float g_bufB[MROWS * EE];     // ffn2 out fp32
__device__ float g_bufT[MROWS * EE];     // t (post layer)
__device__ float g_bufT1[MROWS * EE];    // t1 (post LN1)
__device__ float g_bufFast[MROWS * EE];  // fast path
__device__ float g_pooled[BB * EE];

// fp16 buffers
#define NW_TOTAL 26214400
#define OW_IN   0
#define OW_OUT  6291456
#define OW_F1   8388608
#define OW_F2   16777216
#define OW_FAST 25165824
__device__ __half g_wb_hi[NW_TOTAL];
__device__ __half g_actA_hi[MROWS * 1024];   // narrow activations (hi)
__device__ __half g_actB_hi[MROWS * 4096];   // qkv (3072) / ffn hidden (4096)

__device__ __forceinline__ float gelu_exact(float v) {
    return 0.5f * v * (1.0f + erff(v * 0.7071067811865476f));
}
__device__ __forceinline__ uint32_t pack_f16(float a, float b) {
    __half2 t = __floats2half2_rn(a, b);
    return *(uint32_t*)&t;
}

// =================== portable tensor-core primitives (sm_80+ PTX) ============
__device__ __forceinline__ uint32_t smem_u32(const void* p) {
    uint32_t a;
    asm("{ .reg .u64 t; cvta.to.shared.u64 t, %1; cvt.u32.u64 %0, t; }" : "=r"(a) : "l"(p));
    return a;
}
__device__ __forceinline__ void ldm_x4(uint32_t& r0, uint32_t& r1, uint32_t& r2, uint32_t& r3,
                                       uint32_t addr) {
    asm volatile("ldmatrix.sync.aligned.m8n8.x4.shared.b16 {%0,%1,%2,%3}, [%4];"
                 : "=r"(r0), "=r"(r1), "=r"(r2), "=r"(r3) : "r"(addr));
}
__device__ __forceinline__ void ldm_x4_t(uint32_t& r0, uint32_t& r1, uint32_t& r2, uint32_t& r3,
                                         uint32_t addr) {
    asm volatile("ldmatrix.sync.aligned.m8n8.x4.trans.shared.b16 {%0,%1,%2,%3}, [%4];"
                 : "=r"(r0), "=r"(r1), "=r"(r2), "=r"(r3) : "r"(addr));
}
__device__ __forceinline__ void mma_f32(float* c, uint32_t a0, uint32_t a1, uint32_t a2,
                                        uint32_t a3, uint32_t b0, uint32_t b1) {
    asm volatile(
        "mma.sync.aligned.m16n8k16.row.col.f32.f16.f16.f32 "
        "{%0,%1,%2,%3}, {%4,%5,%6,%7}, {%8,%9}, {%0,%1,%2,%3};"
        : "+f"(c[0]), "+f"(c[1]), "+f"(c[2]), "+f"(c[3])
        : "r"(a0), "r"(a1), "r"(a2), "r"(a3), "r"(b0), "r"(b1));
}
__device__ __forceinline__ void cp16(uint32_t saddr, const void* g) {
    asm volatile("cp.async.cg.shared.global [%0], [%1], 16;" :: "r"(saddr), "l"(g));
}
#define CP_COMMIT() asm volatile("cp.async.commit_group;" ::: "memory")
#define CP_WAIT(N)  asm volatile("cp.async.wait_group %0;" :: "n"(N) : "memory")

// =================== mma.sync GEMM: C[M,N] = Ah[M,K] @ Bh[N,K]^T =============
// Pure fp16 inputs, fp32 accumulate: 1 mma per fragment. 128x128 block,
// 8 warps, K-chunk 32. Stage = 2 tiles (Ah, Bh) = 20480 B; 3 stages
// (loads run two chunks ahead: CP_WAIT(1) tolerates full L2/DRAM latency).
// EPI: 0 fp32, 2 fp16, 3 gelu+fp16,
//      4 fused qkv+fast (cols<3072: fp16 -> Chi stride 3072;
//                        cols>=3072: gelu fp32 -> CF stride 1024, B from BhiF)
#define TIL   10240
#define STAGE (2 * TIL)
#define SMT   (3 * STAGE)          // 61440

__device__ __forceinline__ void copy_tile_async(uint32_t sdst, const __half* __restrict__ g,
                                                int row0, int K, int k0, int tid) {
    #pragma unroll
    for (int i = 0; i < 2; i++) {
        int idx = tid + i * 256;
        int r = idx >> 2, c4 = idx & 3;
        cp16(sdst + r * 80 + c4 * 16, g + (size_t)(row0 + r) * K + k0 + c4 * 8);
    }
}

template<int EPI>
__global__ __launch_bounds__(256, 2) void mma_gemm(
        const __half* __restrict__ Ah,
        const __half* __restrict__ Bhi, const __half* __restrict__ BhiF,
        float* __restrict__ C, __half* __restrict__ Chi,
        float* __restrict__ CF, int N, int K) {
    extern __shared__ __align__(128) char smem[];
    uint32_t sb = smem_u32(smem);
    int tid = threadIdx.x, lane = tid & 31, warp = tid >> 5;
    int wm = warp & 1, wn = warp >> 1;
    int rowB = blockIdx.y * 128, colB = blockIdx.x * 128;

    const __half* BhU = Bhi;
    int bcol = colB;
    bool isFast = false;
    if (EPI == 4 && colB >= 3 * EE) {
        BhU = BhiF; bcol = colB - 3 * EE; isFast = true;
    }

    int aRow = wm * 64 + (lane & 15);
    int aK   = (lane >> 4) * 8;
    uint32_t aOff = (uint32_t)(aRow * 80 + aK * 2);
    int bRow = wn * 32 + ((lane >> 4) << 3) + (lane & 7);
    int bK   = ((lane >> 3) & 1) * 8;
    uint32_t bOff = (uint32_t)(bRow * 80 + bK * 2);

    float acc[4][4][4];
    #pragma unroll
    for (int i = 0; i < 4; i++)
        #pragma unroll
        for (int j = 0; j < 4; j++)
            #pragma unroll
            for (int k = 0; k < 4; k++) acc[i][j][k] = 0.0f;

    int nch = K >> 5;
    // prologue: chunks 0 and 1 in flight
    copy_tile_async(sb + 0 * STAGE + 0 * TIL, Ah,  rowB, K, 0, tid);
    copy_tile_async(sb + 0 * STAGE + 1 * TIL, BhU, bcol, K, 0, tid);
    CP_COMMIT();
    copy_tile_async(sb + 1 * STAGE + 0 * TIL, Ah,  rowB, K, 32, tid);
    copy_tile_async(sb + 1 * STAGE + 1 * TIL, BhU, bcol, K, 32, tid);
    CP_COMMIT();

    for (int c = 0; c < nch; c++) {
        if (c + 1 < nch) { CP_WAIT(1); } else { CP_WAIT(0); }
        __syncthreads();   // chunk c ready for all; all warps done with stage (c+2)%3
        if (c + 2 < nch) {
            uint32_t sn = sb + (uint32_t)(((c + 2) % 3) * STAGE);
            int k0 = (c + 2) * 32;
            copy_tile_async(sn + 0 * TIL, Ah,  rowB, K, k0, tid);
            copy_tile_async(sn + 1 * TIL, BhU, bcol, K, k0, tid);
            CP_COMMIT();
        }

        uint32_t ss = sb + (uint32_t)((c % 3) * STAGE);
        uint32_t sAh = ss + aOff;
        uint32_t sBh = ss + TIL + bOff;

        #pragma unroll
        for (int k16 = 0; k16 < 2; k16++) {
            uint32_t kb = k16 * 32;
            uint32_t bh[2][4];
            #pragma unroll
            for (int nh = 0; nh < 2; nh++) {
                uint32_t off = (uint32_t)(nh * 16 * 80) + kb;
                ldm_x4(bh[nh][0], bh[nh][1], bh[nh][2], bh[nh][3], sBh + off);
            }
            #pragma unroll
            for (int mt = 0; mt < 4; mt++) {
                uint32_t off = (uint32_t)(mt * 16 * 80) + kb;
                uint32_t ah0, ah1, ah2, ah3;
                ldm_x4(ah0, ah1, ah2, ah3, sAh + off);
                #pragma unroll
                for (int nt = 0; nt < 4; nt++) {
                    int nh = nt >> 1, o = (nt & 1) * 2;
                    mma_f32(acc[mt][nt], ah0, ah1, ah2, ah3, bh[nh][o], bh[nh][o + 1]);
                }
            }
        }
    }

    int r = lane >> 2, c2 = (lane & 3) * 2;
    int row0 = rowB + wm * 64;
    #pragma unroll
    for (int mt = 0; mt < 4; mt++)
        #pragma unroll
        for (int nt = 0; nt < 4; nt++) {
            float v0 = acc[mt][nt][0], v1 = acc[mt][nt][1];
            float v2 = acc[mt][nt][2], v3 = acc[mt][nt][3];
            int row = row0 + mt * 16 + r;
            int colLoc = wn * 32 + nt * 8 + c2;
            if (EPI == 4) {
                if (isFast) {
                    v0 = gelu_exact(v0); v1 = gelu_exact(v1);
                    v2 = gelu_exact(v2); v3 = gelu_exact(v3);
                    int col = bcol + colLoc;
                    float2 p0 = {v0, v1}, p1 = {v2, v3};
                    *(float2*)(CF + (size_t)row * EE + col) = p0;
                    *(float2*)(CF + (size_t)(row + 8) * EE + col) = p1;
                } else {
                    int col = colB + colLoc;
                    *(uint32_t*)(Chi + (size_t)row * (3 * EE) + col) = pack_f16(v0, v1);
                    *(uint32_t*)(Chi + (size_t)(row + 8) * (3 * EE) + col) = pack_f16(v2, v3);
                }
            } else if (EPI == 2) {
                int col = colB + colLoc;
                *(uint32_t*)(Chi + (size_t)row * N + col) = pack_f16(v0, v1);
                *(uint32_t*)(Chi + (size_t)(row + 8) * N + col) = pack_f16(v2, v3);
            } else if (EPI == 3) {
                v0 = gelu_exact(v0); v1 = gelu_exact(v1);
                v2 = gelu_exact(v2); v3 = gelu_exact(v3);
                int col = colB + colLoc;
                *(uint32_t*)(Chi + (size_t)row * N + col) = pack_f16(v0, v1);
                *(uint32_t*)(Chi + (size_t)(row + 8) * N + col) = pack_f16(v2, v3);
            } else {
                int col = colB + colLoc;
                float2 p0 = {v0, v1}, p1 = {v2, v3};
                *(float2*)(C + (size_t)row * N + col) = p0;
                *(float2*)(C + (size_t)(row + 8) * N + col) = p1;
            }
        }
}

// =================== tensor-core flash attention (pure fp16) =================
// Q resident; KV triple-buffered via cp.async (2 chunks in flight).
#define ATT_SQ  0              // 128 x 144B = 18432
#define ATT_KV  18432          // stage base; stride 18432 (K 9216 + V 9216)
#define ATT_KSTR 18432
#define KOF_K 0
#define KOF_V 9216
#define ATT_SMEM 73728         // Q + 3 KV stages
#define QSTR 3072

__device__ __forceinline__ void attn_prefetch_kv(uint32_t stageOff,
        const __half* __restrict__ qh, size_t rowbase, int h, int tid, uint32_t sb) {
    #pragma unroll
    for (int i = 0; i < 2; i++) {
        int idx = tid + i * 256;
        int r = idx >> 3, c8 = idx & 7;
        size_t srow = (rowbase + r) * QSTR + h * 64 + c8 * 8;
        uint32_t d = sb + stageOff + (uint32_t)(r * 144 + c8 * 16);
        cp16(d + KOF_K, qh + srow + 1024);
        cp16(d + KOF_V, qh + srow + 2048);
    }
}

__global__ __launch_bounds__(256, 2) void attn_mma(
        const __half* __restrict__ qh, __half* __restrict__ oh) {
    extern __shared__ __align__(128) char smem[];
    uint32_t sb = smem_u32(smem);
    int tid = threadIdx.x, lane = tid & 31, warp = tid >> 5;
    int qt = blockIdx.x, h = blockIdx.y, b = blockIdx.z;
    int rb = b * SS;

    #pragma unroll
    for (int i = 0; i < 4; i++) {
        int idx = tid + i * 256;
        int r = idx >> 3, c8 = idx & 7;
        size_t srow = (size_t)(rb + qt * 128 + r) * QSTR + h * 64 + c8 * 8;
        *(uint4*)(smem + ATT_SQ + r * 144 + c8 * 16) = *(const uint4*)(qh + srow);
    }
    attn_prefetch_kv(ATT_KV + 0 * ATT_KSTR, qh, (size_t)rb, h, tid, sb);
    CP_COMMIT();
    attn_prefetch_kv(ATT_KV + 1 * ATT_KSTR, qh, (size_t)(rb + 64), h, tid, sb);
    CP_COMMIT();

    float m0 = -1e30f, m1 = -1e30f, l0 = 0.0f, l1 = 0.0f;
    float accO[8][4];
    #pragma unroll
    for (int i = 0; i < 8; i++)
        #pragma unroll
        for (int j = 0; j < 4; j++) accO[i][j] = 0.0f;

    uint32_t aAddr = sb + ATT_SQ + (uint32_t)((warp * 16 + (lane & 15)) * 144 + (lane >> 4) * 16);
    uint32_t bOff  = (uint32_t)(((lane & 7) + ((lane >> 4) << 3)) * 144 + ((lane >> 3) & 1) * 16);
    uint32_t vOff  = (uint32_t)(((lane & 7) + ((lane >> 3) & 1) * 8) * 144 + ((lane >> 4) & 1) * 16);

    const int NCH = SS / 64;
    for (int c = 0; c < NCH; c++) {
        if (c + 1 < NCH) { CP_WAIT(1); } else { CP_WAIT(0); }
        __syncthreads();
        if (c + 2 < NCH) {
            attn_prefetch_kv(ATT_KV + (uint32_t)(((c + 2) % 3) * ATT_KSTR),
                             qh, (size_t)(rb + (c + 2) * 64), h, tid, sb);
            CP_COMMIT();
        }
        uint32_t kvB = ATT_KV + (uint32_t)((c % 3) * ATT_KSTR);

        float s[8][4];
        #pragma unroll
        for (int i = 0; i < 8; i++)
            #pragma unroll
            for (int j = 0; j < 4; j++) s[i][j] = 0.0f;

        #pragma unroll
        for (int kc = 0; kc < 4; kc++) {
            uint32_t ah0, ah1, ah2, ah3;
            ldm_x4(ah0, ah1, ah2, ah3, aAddr + kc * 32);
            #pragma unroll
            for (int nh = 0; nh < 4; nh++) {
                uint32_t ba = sb + kvB + KOF_K + (uint32_t)(nh * 16 * 144) + bOff + kc * 32;
                uint32_t bh_[4];
                ldm_x4(bh_[0], bh_[1], bh_[2], bh_[3], ba);
                #pragma unroll
                for (int o = 0; o < 2; o++) {
                    int nt = nh * 2 + o;
                    mma_f32(s[nt], ah0, ah1, ah2, ah3, bh_[o * 2], bh_[o * 2 + 1]);
                }
            }
        }

        float mx0 = -1e30f, mx1 = -1e30f;
        #pragma unroll
        for (int nt = 0; nt < 8; nt++) {
            s[nt][0] *= 0.125f; s[nt][1] *= 0.125f; s[nt][2] *= 0.125f; s[nt][3] *= 0.125f;
            mx0 = fmaxf(mx0, fmaxf(s[nt][0], s[nt][1]));
            mx1 = fmaxf(mx1, fmaxf(s[nt][2], s[nt][3]));
        }
        mx0 = fmaxf(mx0, __shfl_xor_sync(0xffffffffu, mx0, 1));
        mx0 = fmaxf(mx0, __shfl_xor_sync(0xffffffffu, mx0, 2));
        mx1 = fmaxf(mx1, __shfl_xor_sync(0xffffffffu, mx1, 1));
        mx1 = fmaxf(mx1, __shfl_xor_sync(0xffffffffu, mx1, 2));
        float mn0 = fmaxf(m0, mx0), mn1 = fmaxf(m1, mx1);
        float alpha0 = __expf(m0 - mn0), alpha1 = __expf(m1 - mn1);
        m0 = mn0; m1 = mn1;
        float sum0 = 0.0f, sum1 = 0.0f;
        #pragma unroll
        for (int nt = 0; nt < 8; nt++) {
            s[nt][0] = __expf(s[nt][0] - m0);
            s[nt][1] = __expf(s[nt][1] - m0);
            s[nt][2] = __expf(s[nt][2] - m1);
            s[nt][3] = __expf(s[nt][3] - m1);
            sum0 += s[nt][0] + s[nt][1];
            sum1 += s[nt][2] + s[nt][3];
        }
        sum0 += __shfl_xor_sync(0xffffffffu, sum0, 1);
        sum0 += __shfl_xor_sync(0xffffffffu, sum0, 2);
        sum1 += __shfl_xor_sync(0xffffffffu, sum1, 1);
        sum1 += __shfl_xor_sync(0xffffffffu, sum1, 2);
        l0 = l0 * alpha0 + sum0;
        l1 = l1 * alpha1 + sum1;
        #pragma unroll
        for (int dt = 0; dt < 8; dt++) {
            accO[dt][0] *= alpha0; accO[dt][1] *= alpha0;
            accO[dt][2] *= alpha1; accO[dt][3] *= alpha1;
        }

        #pragma unroll
        for (int kc2 = 0; kc2 < 4; kc2++) {
            int n0 = kc2 * 2, n1 = kc2 * 2 + 1;
            uint32_t ph0 = pack_f16(s[n0][0], s[n0][1]);
            uint32_t ph1 = pack_f16(s[n0][2], s[n0][3]);
            uint32_t ph2 = pack_f16(s[n1][0], s[n1][1]);
            uint32_t ph3 = pack_f16(s[n1][2], s[n1][3]);
            #pragma unroll
            for (int nd = 0; nd < 4; nd++) {
                uint32_t va = sb + kvB + KOF_V + (uint32_t)(kc2 * 16 * 144) + vOff + nd * 32;
                uint32_t vh_[4];
                ldm_x4_t(vh_[0], vh_[1], vh_[2], vh_[3], va);
                #pragma unroll
                for (int o = 0; o < 2; o++) {
                    int dt = nd * 2 + o;
                    mma_f32(accO[dt], ph0, ph1, ph2, ph3, vh_[o * 2], vh_[o * 2 + 1]);
                }
            }
        }
    }

    float inv0 = 1.0f / l0, inv1 = 1.0f / l1;
    int g = lane >> 2, c2 = (lane & 3) * 2;
    int row = rb + qt * 128 + warp * 16 + g;
    int colb = h * 64 + c2;
    #pragma unroll
    for (int dt = 0; dt < 8; dt++) {
        float v0 = accO[dt][0] * inv0, v1 = accO[dt][1] * inv0;
        float v2 = accO[dt][2] * inv1, v3 = accO[dt][3] * inv1;
        int col = colb + dt * 8;
        *(uint32_t*)(oh + (size_t)row * EE + col) = pack_f16(v0, v1);
        *(uint32_t*)(oh + (size_t)(row + 8) * EE + col) = pack_f16(v2, v3);
    }
}

// ---------------- fp32 -> fp16 -----------------------------------------------
__global__ __launch_bounds__(256) void convert_kernel(const float* __restrict__ in,
                                                      __half* __restrict__ hi,
                                                      int n4) {
    int i = blockIdx.x * 256 + threadIdx.x;
    if (i >= n4) return;
    float4 v = ((const float4*)in)[i];
    uint2 ho; ho.x = pack_f16(v.x, v.y); ho.y = pack_f16(v.z, v.w);
    ((uint2*)hi)[i] = ho;
}

// ---------------- y = LN(a + b) * g + beta (+ fp16) --------------------------
__global__ __launch_bounds__(256) void add_ln_split_kernel(const float* __restrict__ a,
                                                           const float* __restrict__ bsrc,
                                                           const float* __restrict__ g,
                                                           const float* __restrict__ beta,
                                                           float* __restrict__ y,
                                                           __half* __restrict__ yh) {
    int row = blockIdx.x;
    int tid = threadIdx.x;
    const float* ar = a + (size_t)row * EE;
    const float* br = bsrc + (size_t)row * EE;
    float v[4];
    float s = 0.0f, s2 = 0.0f;
    #pragma unroll
    for (int k = 0; k < 4; k++) {
        float t = ar[tid + 256 * k] + br[tid + 256 * k];
        v[k] = t; s += t; s2 += t * t;
    }
    __shared__ float red[18];
    #pragma unroll
    for (int off = 16; off; off >>= 1) {
        s  += __shfl_xor_sync(0xffffffffu, s,  off);
        s2 += __shfl_xor_sync(0xffffffffu, s2, off);
    }
    int wid = tid >> 5, lid = tid & 31;
    if (lid == 0) { red[wid] = s; red[wid + 8] = s2; }
    __syncthreads();
    if (tid < 32) {
        float a1 = (tid < 8) ? red[tid] : 0.0f;
        float a2 = (tid < 8) ? red[tid + 8] : 0.0f;
        #pragma unroll
        for (int off = 4; off; off >>= 1) {
            a1 += __shfl_xor_sync(0xffffffffu, a1, off);
            a2 += __shfl_xor_sync(0xffffffffu, a2, off);
        }
        if (tid == 0) { red[16] = a1; red[17] = a2; }
    }
    __syncthreads();
    float mu = red[16] * (1.0f / EE);
    float var = red[17] * (1.0f / EE) - mu * mu;
    float rs = rsqrtf(var + 1e-5f);
    float* yr = y + (size_t)row * EE;
    __half* yhr = yh + (size_t)row * EE;
    #pragma unroll
    for (int k = 0; k < 4; k++) {
        int c = tid + 256 * k;
        float val = (v[k] - mu) * rs * g[c] + beta[c];
        yr[c] = val;
        yhr[c] = __float2half_rn(val);
    }
}

// ---------------- mean-pool over S -------------------------------------------
__global__ __launch_bounds__(256) void pool_kernel(const float* __restrict__ x,
                                                   float* __restrict__ pooled) {
    int idx = blockIdx.x * 256 + threadIdx.x;
    int b = idx >> 10, e = idx & 1023;
    const float* p = x + (size_t)b * SS * EE + e;
    float s = 0.0f;
    for (int sI = 0; sI < SS; sI++) s += p[(size_t)sI * EE];
    pooled[idx] = s * (1.0f / SS);
}

// ---------------- complexity estimator ---------------------------------------
__global__ __launch_bounds__(256) void ce_kernel(const float* __restrict__ pooled,
                                                 const float* __restrict__ w1,
                                                 const float* __restrict__ b1,
                                                 const float* __restrict__ w2,
                                                 const float* __restrict__ b2,
                                                 float* __restrict__ out) {
    int b = blockIdx.x, j = threadIdx.x;
    const float* p = pooled + b * EE;
    const float* w = w1 + (size_t)j * EE;
    float s = b1[j];
    for (int k = 0; k < EE; k++) s = fmaf(p[k], w[k], s);
    float h = fmaxf(s, 0.0f);
    __shared__ float red[256];
    red[j] = h * w2[j];
    __syncthreads();
    for (int off = 128; off; off >>= 1) {
        if (j < off) red[j] += red[j + off];
        __syncthreads();
    }
    if (j == 0) {
        float logit = red[0] + b2[0];
        float prob = 1.0f / (1.0f + expf(-logit));
        out[OFF_PROBS + b] = prob;
        out[OFF_MODE + b] = (prob > 0.5f) ? 1.0f : 0.0f;
    }
}

// ---------------- select + mean(mode) ----------------------------------------
__global__ __launch_bounds__(256) void finalize_kernel(const float* __restrict__ t,
                                                       const float* __restrict__ f,
                                                       float* __restrict__ out) {
    size_t i = (size_t)blockIdx.x * 256 + threadIdx.x;
    int b = (int)((i * 4) >> 20);
    float m = out[OFF_MODE + b];
    float4 r = (m > 0.5f) ? ((const float4*)t)[i] : ((const float4*)f)[i];
    ((float4*)out)[i] = r;
    if (i == 0) {
        float sAcc = 0.0f;
        for (int k = 0; k < 8; k++) sAcc += out[OFF_MODE + k];
        out[OFF_MEAN] = sAcc * 0.125f;
    }
}

// -----------------------------------------------------------------------------
extern "C" void kernel_launch(void* const* d_in, const int* in_sizes, int n_in,
                              void* d_out, int out_size) {
    const float* x      = (const float*)d_in[0];
    const float* w_in   = (const float*)d_in[1];
    const float* w_out  = (const float*)d_in[2];
    const float* ffn_w1 = (const float*)d_in[3];
    const float* ffn_w2 = (const float*)d_in[4];
    const float* ln1_g  = (const float*)d_in[5];
    const float* ln1_b  = (const float*)d_in[6];
    const float* ln2_g  = (const float*)d_in[7];
    const float* ln2_b  = (const float*)d_in[8];
    const float* ce_w1  = (const float*)d_in[9];
    const float* ce_b1  = (const float*)d_in[10];
    const float* ce_w2  = (const float*)d_in[11];
    const float* ce_b2  = (const float*)d_in[12];
    const float* fast_w = (const float*)d_in[13];
    float* out = (float*)d_out;

    float *bufA, *bufB, *bufT, *bufT1, *bufFast, *pooled;
    __half *wbh, *ah, *bh;
    cudaGetSymbolAddress((void**)&bufA, g_bufA);
    cudaGetSymbolAddress((void**)&bufB, g_bufB);
    cudaGetSymbolAddress((void**)&bufT, g_bufT);
    cudaGetSymbolAddress((void**)&bufT1, g_bufT1);
    cudaGetSymbolAddress((void**)&bufFast, g_bufFast);
    cudaGetSymbolAddress((void**)&pooled, g_pooled);
    cudaGetSymbolAddress((void**)&wbh, g_wb_hi);
    cudaGetSymbolAddress((void**)&ah, g_actA_hi);
    cudaGetSymbolAddress((void**)&bh, g_actB_hi);

    cudaFuncSetAttribute(mma_gemm<0>, cudaFuncAttributeMaxDynamicSharedMemorySize, SMT);
    cudaFuncSetAttribute(mma_gemm<2>, cudaFuncAttributeMaxDynamicSharedMemorySize, SMT);
    cudaFuncSetAttribute(mma_gemm<3>, cudaFuncAttributeMaxDynamicSharedMemorySize, SMT);
    cudaFuncSetAttribute(mma_gemm<4>, cudaFuncAttributeMaxDynamicSharedMemorySize, SMT);
    cudaFuncSetAttribute(attn_mma, cudaFuncAttributeMaxDynamicSharedMemorySize, ATT_SMEM);

    // convert x -> ah (x itself remains the fp32 residual)
    convert_kernel<<<(MROWS*EE/4)/256, 256>>>(x, ah, MROWS*EE/4);
    // complexity estimator
    pool_kernel<<<(BB * EE) / 256, 256>>>(x, pooled);
    ce_kernel<<<BB, 256>>>(pooled, ce_w1, ce_b1, ce_w2, ce_b2, out);
    // weights: fp16
    convert_kernel<<<(2*3*EE*EE/4)/256, 256>>>(w_in,   wbh + OW_IN,   2*3*EE*EE/4);
    convert_kernel<<<(EE*EE/4)/256,     256>>>(fast_w, wbh + OW_FAST, EE*EE/4);

    const float* tin = x;
    for (int l = 0; l < LL; l++) {
        if (l == 0) {
            mma_gemm<4><<<dim3(4*EE/128, MROWS/128), 256, SMT>>>(
                ah, wbh + OW_IN, wbh + OW_FAST,
                nullptr, bh, bufFast, 4*EE, EE);
        } else {
            mma_gemm<2><<<dim3(3*EE/128, MROWS/128), 256, SMT>>>(
                ah, wbh + OW_IN + (size_t)l*3*EE*EE, nullptr,
                nullptr, bh, nullptr, 3*EE, EE);
        }
        attn_mma<<<dim3(SS/128, HH, BB), 256, ATT_SMEM>>>(bh, ah);
        if (l == 0) {
            convert_kernel<<<(2*EE*EE/4)/256,   256>>>(w_out,  wbh + OW_OUT, 2*EE*EE/4);
            convert_kernel<<<(2*4*EE*EE/4)/256, 256>>>(ffn_w1, wbh + OW_F1,  2*4*EE*EE/4);
            convert_kernel<<<(2*4*EE*EE/4)/256, 256>>>(ffn_w2, wbh + OW_F2,  2*4*EE*EE/4);
        }
        mma_gemm<0><<<dim3(EE/128, MROWS/128), 256, SMT>>>(
            ah, wbh + OW_OUT + (size_t)l*EE*EE, nullptr,
            bufA, nullptr, nullptr, EE, EE);
        add_ln_split_kernel<<<MROWS, 256>>>(tin, bufA, ln1_g + l*EE, ln1_b + l*EE,
                                            bufT1, ah);
        mma_gemm<3><<<dim3(4*EE/128, MROWS/128), 256, SMT>>>(
            ah, wbh + OW_F1 + (size_t)l*4*EE*EE, nullptr,
            nullptr, bh, nullptr, 4*EE, EE);
        mma_gemm<0><<<dim3(EE/128, MROWS/128), 256, SMT>>>(
            bh, wbh + OW_F2 + (size_t)l*4*EE*EE, nullptr,
            bufB, nullptr, nullptr, EE, 4*EE);
        add_ln_split_kernel<<<MROWS, 256>>>(bufT1, bufB, ln2_g + l*EE, ln2_b + l*EE,
                                            bufT, ah);
        tin = bufT;
    }

    finalize_kernel<<<(MROWS * EE / 4) / 256, 256>>>(bufT, bufFast, out);
}